// round 2
// baseline (speedup 1.0000x reference)
#include <cuda_runtime.h>

// Problem constants (fixed shapes per reference)
#define B_  4
#define M_  1024
#define N_  1024
#define DX_ 32
#define H_  32
#define DV_ 64

// Scratch for projected keys/queries (no cudaMalloc allowed)
__device__ __align__(16) float g_k[B_ * N_ * H_];   // [B][N][H]
__device__ __align__(16) float g_q[B_ * M_ * H_];   // [B][M][H]

// ---------------------------------------------------------------------------
// XLA EmitFastTanh (f32, with_fma=true) — bit-faithful replica.
// Clamp to +-7.99881172180175781, Eigen rational p/q with fma Horner,
// IEEE divide, |x| < 0.0004 -> x.
// ---------------------------------------------------------------------------
#define XLA_TANH_CLAMP 7.99881172180175781f

__device__ __forceinline__ float xla_fast_tanh(float x) {
    float xc = fminf(fmaxf(x, -XLA_TANH_CLAMP), XLA_TANH_CLAMP);
    float x2 = xc * xc;
    float p = fmaf(x2, -2.76076847742355e-16f, 2.00018790482477e-13f);
    p = fmaf(x2, p, -8.60467152213735e-11f);
    p = fmaf(x2, p, 5.12229709037114e-08f);
    p = fmaf(x2, p, 1.48572235717979e-05f);
    p = fmaf(x2, p, 6.37261928875436e-04f);
    p = fmaf(x2, p, 4.89352455891786e-03f);
    p = xc * p;
    float q = fmaf(x2, 1.19825839466702e-06f, 1.18534705686654e-04f);
    q = fmaf(x2, q, 2.26843463243900e-03f);
    q = fmaf(x2, q, 4.89352518554385e-03f);
    float t = p / q;                  // IEEE div.rn — must match XLA's fdiv
    if (fabsf(x) < 0.0004f) t = x;    // XLA small-x shortcut
    return t;
}

// ---------------------------------------------------------------------------
// Pass 1: row-wise linear projection  out[row][h] = dot(x[row][:], W[h][:]) + b[h]
// 256 threads = 8 rows x 32 h per block.
// ---------------------------------------------------------------------------
__global__ __launch_bounds__(256) void proj_kernel(
    const float* __restrict__ x,     // [rows][32]
    const float* __restrict__ W,     // [32][32] (h-major)
    const float* __restrict__ bias,  // [32]
    int which                        // 0 -> g_k, 1 -> g_q
) {
    __shared__ float Wt[DX_][H_ + 1];  // Wt[d][h] = W[h][d], padded
    __shared__ float bs[H_];
    __shared__ float xs[8][DX_];

    float* __restrict__ out = which ? g_q : g_k;

    int tid = threadIdx.x;
    for (int i = tid; i < H_ * DX_; i += 256) {
        int h = i >> 5, d = i & 31;
        Wt[d][h] = W[i];
    }
    if (tid < H_) bs[tid] = bias[tid];

    int row0 = blockIdx.x * 8;
    {
        int rr = tid >> 5, d = tid & 31;
        xs[rr][d] = x[(row0 + rr) * DX_ + d];
    }
    __syncthreads();

    int rr = tid >> 5, h = tid & 31;
    float s = bs[h];
    #pragma unroll
    for (int d = 0; d < DX_; d++) s += xs[rr][d] * Wt[d][h];
    out[(row0 + rr) * H_ + h] = s;
}

// ---------------------------------------------------------------------------
// Pass 2: fused laplace-attention.
// Block = (batch, 16-row m tile). 256 threads.
// Thread (m_local = tid>>4, dvl = tid&15):
//   - holds q[m0+m_local][0:32] in registers
//   - accumulates out[m][4*dvl : 4*dvl+4] (float4)
//   - computes weights w[m_local][dvl] and w[m_local][dvl+16] per 32-n chunk
// ---------------------------------------------------------------------------
#define TM 16
#define NB 32

__global__ __launch_bounds__(256) void attn_kernel(
    const float* __restrict__ r_in,   // [B][N][DV]
    float* __restrict__ out           // [B][M][DV]
) {
    __shared__ float4 k_s[NB][9];        // 32 x 8 float4, +1 pad
    __shared__ float4 r_s[NB][16];       // 32 x 64 floats
    __shared__ float  w_s[TM][NB + 1];   // padded: conflict-free STS

    int tid     = threadIdx.x;
    int batch   = blockIdx.x >> 6;            // M_/TM = 64 tiles per batch
    int m0      = (blockIdx.x & 63) * TM;
    int m_local = tid >> 4;
    int dvl     = tid & 15;

    // Saturated weight constant: identical fp32 evaluation to the per-pair
    // path at the clamp, so boundary behavior is bit-consistent.
    const float w_sat = 1.0f + xla_fast_tanh(-XLA_TANH_CLAMP);

    // q row into registers
    float q[H_];
    {
        const float4* qg = (const float4*)(g_q + ((size_t)(batch * M_ + m0 + m_local)) * H_);
        #pragma unroll
        for (int i = 0; i < 8; i++) {
            float4 v = qg[i];
            q[4*i+0] = v.x; q[4*i+1] = v.y; q[4*i+2] = v.z; q[4*i+3] = v.w;
        }
    }

    float4 acc = make_float4(0.f, 0.f, 0.f, 0.f);

    const float4* kg = (const float4*)(g_k + (size_t)batch * N_ * H_);   // [N][8]
    const float4* rg = (const float4*)(r_in + (size_t)batch * N_ * DV_); // [N][16]

    int krow = tid >> 3, kcol = tid & 7;    // 256 threads -> 32x8 float4
    int rrow = tid >> 4, rcol = tid & 15;   // 2 iterations -> 32x16 float4

    for (int n0 = 0; n0 < N_; n0 += NB) {
        // ---- stage chunk into smem ----
        k_s[krow][kcol]      = kg[(size_t)(n0 + krow) * 8 + kcol];
        r_s[rrow][rcol]      = rg[(size_t)(n0 + rrow) * 16 + rcol];
        r_s[rrow + 16][rcol] = rg[(size_t)(n0 + rrow + 16) * 16 + rcol];
        __syncthreads();

        // ---- weights: this thread computes (m_local, dvl) and (m_local, dvl+16) ----
        #pragma unroll
        for (int w = 0; w < 2; ++w) {
            int wn = dvl + 16 * w;
            float s0 = 0.f, s1 = 0.f, s2 = 0.f, s3 = 0.f;
            #pragma unroll
            for (int i = 0; i < 8; i++) {
                float4 kv = k_s[wn][i];
                s0 += fabsf(kv.x - q[4*i+0]);
                s1 += fabsf(kv.y - q[4*i+1]);
                s2 += fabsf(kv.z - q[4*i+2]);
                s3 += fabsf(kv.w - q[4*i+3]);
            }
            float s = (s0 + s1) + (s2 + s3);
            float wv;
            if (s >= XLA_TANH_CLAMP) {
                wv = w_sat;                       // ~100% of pairs
            } else {
                wv = 1.0f + xla_fast_tanh(-s);    // rare transition region
            }
            w_s[m_local][wn] = wv;
        }
        __syncthreads();

        // ---- accumulate rep over this n chunk ----
        #pragma unroll
        for (int n = 0; n < NB; ++n) {
            float  wv = w_s[m_local][n];
            float4 rv = r_s[n][dvl];
            acc.x += wv * rv.x;
            acc.y += wv * rv.y;
            acc.z += wv * rv.z;
            acc.w += wv * rv.w;
        }
        __syncthreads();
    }

    float4* og = (float4*)out;
    og[(size_t)(batch * M_ + m0 + m_local) * (DV_ / 4) + dvl] = acc;
}

// ---------------------------------------------------------------------------
// Launch: bind inputs by element count (robust to metadata ordering).
//   x1 = first 131072, x2 = second 131072, r = 262144, W = 1024, b = 32
// ---------------------------------------------------------------------------
extern "C" void kernel_launch(void* const* d_in, const int* in_sizes, int n_in,
                              void* d_out, int out_size) {
    const float* x1 = nullptr;
    const float* x2 = nullptr;
    const float* r  = nullptr;
    const float* W  = nullptr;
    const float* b  = nullptr;

    for (int i = 0; i < n_in; i++) {
        int sz = in_sizes[i];
        const float* p = (const float*)d_in[i];
        if (sz == B_ * N_ * DV_)      { r = p; }
        else if (sz == H_ * DX_)      { W = p; }
        else if (sz == H_)            { b = p; }
        else if (sz == B_ * N_ * DX_) { if (!x1) x1 = p; else x2 = p; }
    }
    // Fallback to positional if anything missing
    if (!x1 || !x2 || !r || !W || !b) {
        x1 = (const float*)d_in[0];
        x2 = (const float*)d_in[1];
        r  = (const float*)d_in[2];
        W  = (const float*)d_in[3];
        b  = (const float*)d_in[4];
    }

    float* out = (float*)d_out;
    (void)out_size;

    proj_kernel<<<(B_ * N_) / 8, 256>>>(x1, W, b, 0);  // -> g_k
    proj_kernel<<<(B_ * M_) / 8, 256>>>(x2, W, b, 1);  // -> g_q
    attn_kernel<<<B_ * (M_ / TM), 256>>>(r, out);
}

// round 3
// speedup vs baseline: 2.8094x; 2.8094x over previous
#include <cuda_runtime.h>

// Problem constants (fixed shapes per reference)
#define B_  4
#define M_  1024
#define N_  1024
#define DX_ 32
#define H_  32
#define DV_ 64

#define XLA_TANH_CLAMP 7.99881172180175781f

// Scratch (no cudaMalloc allowed)
__device__ __align__(16) float g_k[B_ * N_ * H_];   // [B][N][H]
__device__ __align__(16) float g_q[B_ * M_ * H_];   // [B][M][H]
__device__ __align__(16) float g_S[B_ * DV_];       // [B][64]  Sum_n r[b][n][v]

// ---------------------------------------------------------------------------
// XLA EmitFastTanh (f32, with_fma=true) — bit-faithful replica.
// ---------------------------------------------------------------------------
__device__ __forceinline__ float xla_fast_tanh(float x) {
    float xc = fminf(fmaxf(x, -XLA_TANH_CLAMP), XLA_TANH_CLAMP);
    float x2 = xc * xc;
    float p = fmaf(x2, -2.76076847742355e-16f, 2.00018790482477e-13f);
    p = fmaf(x2, p, -8.60467152213735e-11f);
    p = fmaf(x2, p, 5.12229709037114e-08f);
    p = fmaf(x2, p, 1.48572235717979e-05f);
    p = fmaf(x2, p, 6.37261928875436e-04f);
    p = fmaf(x2, p, 4.89352455891786e-03f);
    p = xc * p;
    float q = fmaf(x2, 1.19825839466702e-06f, 1.18534705686654e-04f);
    q = fmaf(x2, q, 2.26843463243900e-03f);
    q = fmaf(x2, q, 4.89352518554385e-03f);
    float t = p / q;                  // IEEE div.rn
    if (fabsf(x) < 0.0004f) t = x;
    return t;
}

// ---------------------------------------------------------------------------
// Packed f32x2 helpers (Blackwell sm_100a+)
// ---------------------------------------------------------------------------
__device__ __forceinline__ unsigned long long pk2(float lo, float hi) {
    unsigned long long r;
    asm("mov.b64 %0, {%1, %2};" : "=l"(r) : "f"(lo), "f"(hi));
    return r;
}
__device__ __forceinline__ unsigned long long add2(unsigned long long a,
                                                   unsigned long long b) {
    unsigned long long d;
    asm("add.rn.f32x2 %0, %1, %2;" : "=l"(d) : "l"(a), "l"(b));
    return d;
}
__device__ __forceinline__ float hsum2(unsigned long long a) {
    float lo, hi;
    asm("mov.b64 {%0, %1}, %2;" : "=f"(lo), "=f"(hi) : "l"(a));
    return lo + hi;
}
#define ABS2_MASK 0x7FFFFFFF7FFFFFFFULL

// ---------------------------------------------------------------------------
// Kernel A (one launch): projections k = x1 W^T + b, q = x2 W^T + b, and
// column sums S[b][v] = Sum_n r[b][n][v].
//   blocks 0..127   : k rows (32 rows/block)
//   blocks 128..255 : q rows
//   blocks 256..259 : S sums (one batch each)
// ---------------------------------------------------------------------------
__global__ __launch_bounds__(256) void prep_kernel(
    const float* __restrict__ x1,
    const float* __restrict__ x2,
    const float* __restrict__ r_in,
    const float* __restrict__ W,
    const float* __restrict__ bias
) {
    __shared__ float Wt[DX_][H_ + 1];   // Wt[d][h] = W[h][d]
    __shared__ float bs[H_];
    __shared__ float xs[32 * DX_];      // 32 rows of x
    __shared__ float psum[4][DV_];

    int tid = threadIdx.x;
    int b   = blockIdx.x;

    if (b >= 256) {
        // ---- S sums ----
        int batch = b - 256;
        int v    = tid & 63;
        int part = tid >> 6;            // 0..3, 256 n each
        const float* rp = r_in + ((size_t)batch * N_ + part * 256) * DV_ + v;
        float s = 0.f;
        #pragma unroll 8
        for (int n = 0; n < 256; n++) s += rp[n * DV_];
        psum[part][v] = s;
        __syncthreads();
        if (tid < DV_) {
            float t = ((psum[0][tid] + psum[1][tid]) + psum[2][tid]) + psum[3][tid];
            g_S[batch * DV_ + tid] = t;
        }
        return;
    }

    // ---- projection ----
    int which = (b >= 128);
    const float* __restrict__ x   = which ? x2 : x1;
    float* __restrict__       outp = which ? g_q : g_k;
    int row0 = (b & 127) * 32;

    for (int i = tid; i < H_ * DX_; i += 256) {
        int h = i >> 5, d = i & 31;
        Wt[d][h] = W[i];
    }
    if (tid < H_) bs[tid] = bias[tid];
    #pragma unroll
    for (int i = tid; i < 32 * DX_; i += 256) xs[i] = x[row0 * DX_ + i];
    __syncthreads();

    int h  = tid & 31;
    int rg = tid >> 5;                  // 8 groups x 4 rows
    #pragma unroll
    for (int j = 0; j < 4; j++) {
        int row = rg * 4 + j;
        float s = bs[h];
        #pragma unroll
        for (int d = 0; d < DX_; d++) s += xs[row * DX_ + d] * Wt[d][h];
        outp[(row0 + row) * H_ + h] = s;
    }
}

// ---------------------------------------------------------------------------
// Kernel B: s-matrix + saturated output.
// Block = (batch, 32-row m tile). 512 threads = 16 warps; warp owns 2 m rows.
// Lane computes s(m, n) for n = chunk + n_sub*32 + lane over all N.
// Output: out[m][v] = w_sat * S[v] + corr[m][v] (corr from rare s<clamp pairs).
// ---------------------------------------------------------------------------
#define TM 32
#define NB 128
#define NP2 (NB + 1)

// Cold path: recompute s for one (m,n) pair from global and apply correction.
__device__ __noinline__ void fix_pair(
    float* corr_row, const float* __restrict__ r_in,
    int batch, int m, int n, float w_sat
) {
    const float* kp = g_k + ((size_t)batch * N_ + n) * H_;
    const float* qp = g_q + ((size_t)batch * M_ + m) * H_;
    float s = 0.f;
    for (int hh = 0; hh < H_; hh++) s += fabsf(kp[hh] - qp[hh]);
    if (s < XLA_TANH_CLAMP) {
        float w = 1.0f + xla_fast_tanh(-s);
        float delta = w - w_sat;
        const float* rp = r_in + ((size_t)batch * N_ + n) * DV_;
        for (int v = 0; v < DV_; v++) atomicAdd(&corr_row[v], delta * rp[v]);
    }
}

__global__ __launch_bounds__(512) void attn_s_kernel(
    const float* __restrict__ r_in,   // [B][N][DV]
    float* __restrict__ out           // [B][M][DV]
) {
    __shared__ float2 k2[H_ / 2][NP2];   // transposed h-pair-major k chunk
    __shared__ float  corr[TM][DV_];     // rare-exception corrections

    int tid   = threadIdx.x;
    int warp  = tid >> 5;
    int lane  = tid & 31;
    int batch = blockIdx.x >> 5;         // 32 m-tiles per batch
    int mtile = blockIdx.x & 31;
    int m0    = mtile * TM + warp * 2;   // warp's two m rows

    const float w_sat = 1.0f + xla_fast_tanh(-XLA_TANH_CLAMP);

    // zero correction accumulator
    for (int i = tid; i < TM * DV_; i += 512) ((float*)corr)[i] = 0.f;

    // negated q for both rows, packed as h-pairs
    unsigned long long nq0[H_ / 2], nq1[H_ / 2];
    {
        const float2* q0 = (const float2*)(g_q + ((size_t)batch * M_ + m0) * H_);
        const float2* q1 = (const float2*)(g_q + ((size_t)batch * M_ + m0 + 1) * H_);
        #pragma unroll
        for (int i = 0; i < H_ / 2; i++) {
            float2 a = q0[i], c = q1[i];
            nq0[i] = pk2(-a.x, -a.y);
            nq1[i] = pk2(-c.x, -c.y);
        }
    }

    const float4* kg4 = (const float4*)(g_k + (size_t)batch * N_ * H_);  // [N][8]

    // staging indices: 1024 float4 per chunk, 2 per thread
    int idxA = tid, idxB = tid + 512;
    int nA = idxA >> 3, hA = idxA & 7;
    int nB = idxB >> 3, hB = idxB & 7;

    float4 pfA = kg4[(size_t)nA * 8 + hA];       // prefetch chunk 0
    float4 pfB = kg4[(size_t)nB * 8 + hB];

    float smin = 1e30f;

    for (int c = 0; c < N_ / NB; c++) {
        __syncthreads();                          // smem free (also covers corr zero)
        k2[2 * hA][nA]     = make_float2(pfA.x, pfA.y);
        k2[2 * hA + 1][nA] = make_float2(pfA.z, pfA.w);
        k2[2 * hB][nB]     = make_float2(pfB.x, pfB.y);
        k2[2 * hB + 1][nB] = make_float2(pfB.z, pfB.w);
        __syncthreads();

        if (c + 1 < N_ / NB) {
            size_t base = (size_t)(c + 1) * NB * 8;
            pfA = kg4[base + (size_t)nA * 8 + hA];
            pfB = kg4[base + (size_t)nB * 8 + hB];
        }

        for (int n_sub = 0; n_sub < NB / 32; n_sub++) {
            int n_loc = n_sub * 32 + lane;
            unsigned long long a0 = 0, a1 = 0, b0 = 0, b1 = 0;
            #pragma unroll
            for (int h2 = 0; h2 < H_ / 2; h2++) {
                unsigned long long kv =
                    *reinterpret_cast<const unsigned long long*>(&k2[h2][n_loc]);
                unsigned long long d0 = add2(kv, nq0[h2]) & ABS2_MASK;
                unsigned long long d1 = add2(kv, nq1[h2]) & ABS2_MASK;
                if (h2 & 1) { a1 = add2(a1, d0); b1 = add2(b1, d1); }
                else        { a0 = add2(a0, d0); b0 = add2(b0, d1); }
            }
            float s0 = hsum2(add2(a0, a1));
            float s1 = hsum2(add2(b0, b1));
            smin = fminf(smin, fminf(s0, s1));
        }
    }

    // Rare path: if any s for this lane's (m,n) set dipped below the clamp,
    // rescan those pairs from global and accumulate exact corrections.
    if (smin < XLA_TANH_CLAMP) {
        for (int c = 0; c < N_ / NB; c++)
            for (int n_sub = 0; n_sub < NB / 32; n_sub++) {
                int n = c * NB + n_sub * 32 + lane;
                fix_pair(corr[warp * 2 + 0], r_in, batch, m0,     n, w_sat);
                fix_pair(corr[warp * 2 + 1], r_in, batch, m0 + 1, n, w_sat);
            }
    }
    __syncthreads();

    // out[m][v] = w_sat * S[v] + corr[m][v]
    const float* Sp = g_S + batch * DV_;
    float* op = out + ((size_t)batch * M_ + mtile * TM) * DV_;
    for (int i = tid; i < TM * DV_; i += 512) {
        int ml = i >> 6, v = i & 63;
        op[(size_t)ml * DV_ + v] = fmaf(w_sat, Sp[v], corr[ml][v]);
    }
}

// ---------------------------------------------------------------------------
// Launch: bind inputs by element count (robust to metadata ordering).
// ---------------------------------------------------------------------------
extern "C" void kernel_launch(void* const* d_in, const int* in_sizes, int n_in,
                              void* d_out, int out_size) {
    const float* x1 = nullptr;
    const float* x2 = nullptr;
    const float* r  = nullptr;
    const float* W  = nullptr;
    const float* b  = nullptr;

    for (int i = 0; i < n_in; i++) {
        int sz = in_sizes[i];
        const float* p = (const float*)d_in[i];
        if (sz == B_ * N_ * DV_)      { r = p; }
        else if (sz == H_ * DX_)      { W = p; }
        else if (sz == H_)            { b = p; }
        else if (sz == B_ * N_ * DX_) { if (!x1) x1 = p; else x2 = p; }
    }
    if (!x1 || !x2 || !r || !W || !b) {
        x1 = (const float*)d_in[0];
        x2 = (const float*)d_in[1];
        r  = (const float*)d_in[2];
        W  = (const float*)d_in[3];
        b  = (const float*)d_in[4];
    }

    float* out = (float*)d_out;
    (void)out_size;

    prep_kernel<<<260, 256>>>(x1, x2, r, W, b);          // k, q, S
    attn_s_kernel<<<B_ * (M_ / TM), 512>>>(r, out);      // s-matrix + output
}